// round 13
// baseline (speedup 1.0000x reference)
#include <cuda_runtime.h>
#include <cuda_bf16.h>
#include <cstdint>

#define N_NODES 100000
#define N_EDGES 2048
#define L_TOK 8
#define HID 64
#define D_IN 512      // L_TOK * HID
#define D_GNN 128
#define VOCAB 32000
#define FFN_D 256
#define NROWS (N_EDGES * 2)   // 4096 lm-head rows
#define LBL_OFF 16384         // labels occupy [0, 16384)

// ---------------- device scratch (no allocations allowed) ----------------
// Invariant: g_agg (touched rows) and g_rowsum are ZERO at kernel_launch entry.
// Statically zero-initialized; re-zeroed by k6_fin at the end of every call.
__device__ float g_agg[N_NODES * D_GNN];
__device__ uint32_t g_xf[256 * 4 * 128];          // x in bf16x2 fragment-major
__device__ float g_rowsum[NROWS];

__device__ __forceinline__ uint32_t pack_bf16x2(float lo, float hi) {
    __nv_bfloat162 b = __float22bfloat162_rn(make_float2(lo, hi));
    return *(uint32_t*)&b;
}

// ---------------- K1: msg = (node_emb[src] + edge_emb) @ W_nbr; scatter-add at dst ----------------
#define K1_EDGES 8
__global__ __launch_bounds__(256) void k1_msg(const int* __restrict__ node_tokens,
                                              const int* __restrict__ edge_tokens,
                                              const int* __restrict__ edge_index,
                                              const float* __restrict__ emb,
                                              const float* __restrict__ W_nbr) {
    __shared__ float t_s[K1_EDGES][D_IN];
    __shared__ int s_src[K1_EDGES], s_dst[K1_EDGES];
    int b = blockIdx.x, tid = threadIdx.x;
    int e0 = b * K1_EDGES;
    if (tid < K1_EDGES) {
        s_src[tid] = edge_index[e0 + tid];
        s_dst[tid] = edge_index[N_EDGES + e0 + tid];
    }
    __syncthreads();
    for (int idx = tid; idx < K1_EDGES * D_IN; idx += 256) {
        int el = idx >> 9, kk = idx & 511;
        int l = kk >> 6, h = kk & 63;
        int tn = node_tokens[s_src[el] * L_TOK + l];
        int te = edge_tokens[(e0 + el) * L_TOK + l];
        t_s[el][kk] = emb[tn * HID + h] + emb[te * HID + h];
    }
    __syncthreads();
    int c = tid & 127, p = tid >> 7;
    float a0 = 0.f, a1 = 0.f, a2 = 0.f, a3 = 0.f;
    const float* t0 = t_s[4 * p + 0];
    const float* t1 = t_s[4 * p + 1];
    const float* t2 = t_s[4 * p + 2];
    const float* t3 = t_s[4 * p + 3];
#pragma unroll 8
    for (int k = 0; k < D_IN; k++) {
        float w = W_nbr[k * D_GNN + c];
        a0 += t0[k] * w;
        a1 += t1[k] * w;
        a2 += t2[k] * w;
        a3 += t3[k] * w;
    }
    atomicAdd(&g_agg[s_dst[4 * p + 0] * D_GNN + c], a0);
    atomicAdd(&g_agg[s_dst[4 * p + 1] * D_GNN + c], a1);
    atomicAdd(&g_agg[s_dst[4 * p + 2] * D_GNN + c], a2);
    atomicAdd(&g_agg[s_dst[4 * p + 3] * D_GNN + c], a3);
}

// ---------------- K3: fused GNN-h + transformer; WARP PER EDGE (2 rows/warp) ----------------
__global__ __launch_bounds__(128) void k3_fused(const int* __restrict__ node_tokens,
                                                const int* __restrict__ edge_index,
                                                const float* __restrict__ emb,
                                                const float* __restrict__ W_self,
                                                const float* __restrict__ Wq, const float* __restrict__ Wk,
                                                const float* __restrict__ Wv, const float* __restrict__ Wo,
                                                const float* __restrict__ W1, const float* __restrict__ W2) {
    __shared__ float ne[8][D_IN];
    __shared__ float hn[8][D_GNN];
    __shared__ int snode[8];
    __shared__ float xsm[4][2][64];
    __shared__ float hsm[4][2][FFN_D];

    int tid = threadIdx.x, lane = tid & 31, wid = tid >> 5;
    int e_base = blockIdx.x * 4;

    if (tid < 8)
        snode[tid] = edge_index[(tid & 1) * N_EDGES + e_base + (tid >> 1)];
    __syncthreads();

    for (int idx = tid; idx < 8 * D_IN; idx += 128) {
        int j = idx >> 9, kk = idx & 511;
        int l = kk >> 6, hcol = kk & 63;
        int tok = node_tokens[snode[j] * L_TOK + l];
        ne[j][kk] = emb[tok * HID + hcol];
    }
    __syncthreads();

    {
        int c = tid;
        float acc[8];
#pragma unroll
        for (int j = 0; j < 8; j++) acc[j] = 0.f;
#pragma unroll 2
        for (int k4i = 0; k4i < D_IN / 4; k4i++) {
            const float* wr = W_self + k4i * 4 * D_GNN + c;
            float w0 = wr[0], w1 = wr[D_GNN], w2 = wr[2 * D_GNN], w3 = wr[3 * D_GNN];
#pragma unroll
            for (int j = 0; j < 8; j++) {
                float4 a = ((const float4*)ne[j])[k4i];
                acc[j] += a.x * w0 + a.y * w1 + a.z * w2 + a.w * w3;
            }
        }
#pragma unroll
        for (int j = 0; j < 8; j++)
            hn[j][c] = fmaxf(acc[j] + g_agg[snode[j] * D_GNN + c], 0.f);
    }
    __syncthreads();

    int e = e_base + wid;
    float2 s0a = ((const float2*)&hn[2 * wid][0])[lane];
    float2 s0b = ((const float2*)&hn[2 * wid + 1][0])[lane];
    float2 s1a = ((const float2*)&hn[2 * wid][64])[lane];
    float2 s1b = ((const float2*)&hn[2 * wid + 1][64])[lane];
    float x00 = s0a.x + s0b.x, x01 = s0a.y + s0b.y;
    float x10 = s1a.x + s1b.x, x11 = s1a.y + s1b.y;
    xsm[wid][0][2 * lane] = x00; xsm[wid][0][2 * lane + 1] = x01;
    xsm[wid][1][2 * lane] = x10; xsm[wid][1][2 * lane + 1] = x11;
    __syncwarp();

    const float2* Wq2 = (const float2*)Wq;
    const float2* Wk2 = (const float2*)Wk;
    const float2* Wv2 = (const float2*)Wv;
    const float2* Wo2 = (const float2*)Wo;
    const float2* W22 = (const float2*)W2;

    float q00 = 0.f, q01 = 0.f, k00 = 0.f, k01 = 0.f, v00 = 0.f, v01 = 0.f;
    float q10 = 0.f, q11 = 0.f, k10 = 0.f, k11 = 0.f, v10 = 0.f, v11 = 0.f;
#pragma unroll 4
    for (int k = 0; k < 64; k++) {
        float xa = xsm[wid][0][k], xb = xsm[wid][1][k];
        float2 wq = Wq2[k * 32 + lane];
        float2 wk = Wk2[k * 32 + lane];
        float2 wv = Wv2[k * 32 + lane];
        q00 += xa * wq.x; q01 += xa * wq.y; q10 += xb * wq.x; q11 += xb * wq.y;
        k00 += xa * wk.x; k01 += xa * wk.y; k10 += xb * wk.x; k11 += xb * wk.y;
        v00 += xa * wv.x; v01 += xa * wv.y; v10 += xb * wv.x; v11 += xb * wv.y;
    }

    float p00 = q00 * k00 + q01 * k01;
    float p01 = q00 * k10 + q01 * k11;
    float p10 = q10 * k00 + q11 * k01;
    float p11 = q10 * k10 + q11 * k11;
#pragma unroll
    for (int d = 16; d; d >>= 1) {
        p00 += __shfl_xor_sync(0xffffffffu, p00, d);
        p01 += __shfl_xor_sync(0xffffffffu, p01, d);
        p10 += __shfl_xor_sync(0xffffffffu, p10, d);
        p11 += __shfl_xor_sync(0xffffffffu, p11, d);
    }
    p00 *= 0.125f; p01 *= 0.125f; p10 *= 0.125f; p11 *= 0.125f;
    float m0 = fmaxf(p00, p01), m1 = fmaxf(p10, p11);
    float e00 = __expf(p00 - m0), e01 = __expf(p01 - m0);
    float e10 = __expf(p10 - m1), e11 = __expf(p11 - m1);
    float i0 = 1.f / (e00 + e01), i1 = 1.f / (e10 + e11);
    float a00 = e00 * i0, a01 = e01 * i0;
    float a10 = e10 * i1, a11 = e11 * i1;

    float y00 = a00 * v00 + a01 * v10, y01 = a00 * v01 + a01 * v11;
    float y10 = a10 * v00 + a11 * v10, y11 = a10 * v01 + a11 * v11;

    xsm[wid][0][2 * lane] = y00; xsm[wid][0][2 * lane + 1] = y01;
    xsm[wid][1][2 * lane] = y10; xsm[wid][1][2 * lane + 1] = y11;
    __syncwarp();

    float o00 = 0.f, o01 = 0.f, o10 = 0.f, o11 = 0.f;
#pragma unroll 4
    for (int k = 0; k < 64; k++) {
        float ya = xsm[wid][0][k], yb = xsm[wid][1][k];
        float2 wo = Wo2[k * 32 + lane];
        o00 += ya * wo.x; o01 += ya * wo.y;
        o10 += yb * wo.x; o11 += yb * wo.y;
    }
    x00 += o00; x01 += o01; x10 += o10; x11 += o11;

    float ms0 = x00 + x01, ms1 = x10 + x11;
#pragma unroll
    for (int d = 16; d; d >>= 1) {
        ms0 += __shfl_xor_sync(0xffffffffu, ms0, d);
        ms1 += __shfl_xor_sync(0xffffffffu, ms1, d);
    }
    float mean0 = ms0 * (1.f / 64.f), mean1 = ms1 * (1.f / 64.f);
    float d00 = x00 - mean0, d01 = x01 - mean0;
    float d10 = x10 - mean1, d11 = x11 - mean1;
    float vs0 = d00 * d00 + d01 * d01, vs1 = d10 * d10 + d11 * d11;
#pragma unroll
    for (int d = 16; d; d >>= 1) {
        vs0 += __shfl_xor_sync(0xffffffffu, vs0, d);
        vs1 += __shfl_xor_sync(0xffffffffu, vs1, d);
    }
    float r0 = rsqrtf(vs0 * (1.f / 64.f) + 1e-5f);
    float r1 = rsqrtf(vs1 * (1.f / 64.f) + 1e-5f);
    x00 = d00 * r0; x01 = d01 * r0;
    x10 = d10 * r1; x11 = d11 * r1;

    __syncwarp();
    xsm[wid][0][2 * lane] = x00; xsm[wid][0][2 * lane + 1] = x01;
    xsm[wid][1][2 * lane] = x10; xsm[wid][1][2 * lane + 1] = x11;
    __syncwarp();

    float h[2][8];
#pragma unroll
    for (int j = 0; j < 8; j++) { h[0][j] = 0.f; h[1][j] = 0.f; }
#pragma unroll 4
    for (int k = 0; k < 64; k++) {
        float xa = xsm[wid][0][k], xb = xsm[wid][1][k];
        const float* w1r = W1 + k * FFN_D + lane;
#pragma unroll
        for (int j = 0; j < 8; j++) {
            float w = w1r[j * 32];
            h[0][j] += xa * w;
            h[1][j] += xb * w;
        }
    }
#pragma unroll
    for (int j = 0; j < 8; j++) {
        hsm[wid][0][j * 32 + lane] = fmaxf(h[0][j], 0.f);
        hsm[wid][1][j * 32 + lane] = fmaxf(h[1][j], 0.f);
    }
    __syncwarp();

    float o200 = 0.f, o201 = 0.f, o210 = 0.f, o211 = 0.f;
#pragma unroll 8
    for (int f = 0; f < FFN_D; f++) {
        float ha = hsm[wid][0][f], hb = hsm[wid][1][f];
        float2 w2 = W22[f * 32 + lane];
        o200 += ha * w2.x; o201 += ha * w2.y;
        o210 += hb * w2.x; o211 += hb * w2.y;
    }
    float z00 = x00 + o200, z01 = x01 + o201;
    float z10 = x10 + o210, z11 = x11 + o211;

    ms0 = z00 + z01; ms1 = z10 + z11;
#pragma unroll
    for (int d = 16; d; d >>= 1) {
        ms0 += __shfl_xor_sync(0xffffffffu, ms0, d);
        ms1 += __shfl_xor_sync(0xffffffffu, ms1, d);
    }
    mean0 = ms0 * (1.f / 64.f); mean1 = ms1 * (1.f / 64.f);
    d00 = z00 - mean0; d01 = z01 - mean0;
    d10 = z10 - mean1; d11 = z11 - mean1;
    vs0 = d00 * d00 + d01 * d01; vs1 = d10 * d10 + d11 * d11;
#pragma unroll
    for (int d = 16; d; d >>= 1) {
        vs0 += __shfl_xor_sync(0xffffffffu, vs0, d);
        vs1 += __shfl_xor_sync(0xffffffffu, vs1, d);
    }
    r0 = rsqrtf(vs0 * (1.f / 64.f) + 1e-5f);
    r1 = rsqrtf(vs1 * (1.f / 64.f) + 1e-5f);

    {
        int ks = lane >> 3, pr = lane & 7, hi = pr >> 2, tg = pr & 3;
        int frag = ks * 128 + tg * 2 + hi;
#pragma unroll
        for (int s = 0; s < 2; s++) {
            int rr = e * 2 + s;
            int rt16 = rr >> 4, half = (rr & 15) >> 3, gg = rr & 7;
            float lo = (s == 0 ? d00 * r0 : d10 * r1);
            float hi2 = (s == 0 ? d01 * r0 : d11 * r1);
            g_xf[rt16 * 512 + frag + half * 64 + gg * 8] = pack_bf16x2(lo, hi2);
        }
    }
}

// ---------------- K4: lm head, bf16 m16n8k16; column-split accumulators for 3 blocks/SM ----------------
#define K4_ROW_ITERS 8

template <bool STORE>
__global__ __launch_bounds__(256, 3) void k4_tc(const float* __restrict__ lmW,
                                                const float* __restrict__ lmb,
                                                float* __restrict__ out) {
    __shared__ uint32_t Bs[4096];
    __shared__ float bsm[128];

    int tid = threadIdx.x;
    int cb = blockIdx.x * 128;

    for (int i = tid; i < 4096; i += 256) {
        int n = i & 127, w = i >> 7;
        float v0 = lmW[(size_t)(2 * w) * VOCAB + cb + n];
        float v1 = lmW[(size_t)(2 * w + 1) * VOCAB + cb + n];
        int nt = n >> 3, gg = n & 7;
        int ks = w >> 3, pr = w & 7, hi = pr >> 2, tg = pr & 3;
        Bs[(nt * 4 + ks) * 64 + gg * 8 + tg * 2 + hi] = pack_bf16x2(v0, v1);
    }
    if (tid < 128) bsm[tid] = lmb[cb + tid];
    __syncthreads();

    int lane = tid & 31, warp = tid >> 5;
    int wm = warp >> 1, wn = warp & 1;
    int g = lane >> 2, tig = lane & 3;

#pragma unroll 1
    for (int it = 0; it < K4_ROW_ITERS; it++) {
        int rb = (blockIdx.y * K4_ROW_ITERS + it) * 128;
        int rt16b = rb >> 4;

        float slo0 = 0.f, shi0 = 0.f, slo1 = 0.f, shi1 = 0.f;

#pragma unroll
        for (int half = 0; half < 2; half++) {
            float acc[2][4][4];
#pragma unroll
            for (int mt = 0; mt < 2; mt++)
#pragma unroll
                for (int nt = 0; nt < 4; nt++)
#pragma unroll
                    for (int j = 0; j < 4; j++) acc[mt][nt][j] = 0.f;

#pragma unroll
            for (int ks = 0; ks < 4; ks++) {
                uint32_t a[2][4];
#pragma unroll
                for (int mt = 0; mt < 2; mt++) {
                    const uint32_t* ap = g_xf + ((rt16b + wm * 2 + mt) * 4 + ks) * 128;
                    uint2 p0 = __ldg((const uint2*)(ap + lane * 2));
                    uint2 p1 = __ldg((const uint2*)(ap + 64 + lane * 2));
                    a[mt][0] = p0.x; a[mt][2] = p0.y; a[mt][1] = p1.x; a[mt][3] = p1.y;
                }
#pragma unroll
                for (int nt = 0; nt < 4; nt++) {
                    const uint32_t* bp = Bs + ((wn * 8 + half * 4 + nt) * 4 + ks) * 64;
                    uint2 bb = *(const uint2*)(bp + lane * 2);
#pragma unroll
                    for (int mt = 0; mt < 2; mt++) {
                        asm volatile(
                            "mma.sync.aligned.m16n8k16.row.col.f32.bf16.bf16.f32 "
                            "{%0,%1,%2,%3}, {%4,%5,%6,%7}, {%8,%9}, {%0,%1,%2,%3};\n"
                            : "+f"(acc[mt][nt][0]), "+f"(acc[mt][nt][1]),
                              "+f"(acc[mt][nt][2]), "+f"(acc[mt][nt][3])
                            : "r"(a[mt][0]), "r"(a[mt][1]), "r"(a[mt][2]), "r"(a[mt][3]),
                              "r"(bb.x), "r"(bb.y));
                    }
                }
            }

            // epilogue for this 32-col half
#pragma unroll
            for (int mt = 0; mt < 2; mt++) {
                int r_lo = rb + wm * 32 + mt * 16 + g;
                int cb2 = wn * 64 + half * 32 + 2 * tig;
                if (STORE) {
                    float inv_lo = 1.f / g_rowsum[r_lo];
                    float inv_hi = 1.f / g_rowsum[r_lo + 8];
                    float* plo = out + (size_t)LBL_OFF + (size_t)r_lo * VOCAB + cb + cb2;
                    float* phi = plo + (size_t)8 * VOCAB;
#pragma unroll
                    for (int nt = 0; nt < 4; nt++) {
                        float2 bv = *(const float2*)&bsm[cb2 + nt * 8];
                        float e0 = __expf(acc[mt][nt][0] + bv.x) * inv_lo;
                        float e1 = __expf(acc[mt][nt][1] + bv.y) * inv_lo;
                        float e2 = __expf(acc[mt][nt][2] + bv.x) * inv_hi;
                        float e3 = __expf(acc[mt][nt][3] + bv.y) * inv_hi;
                        __stcs((float2*)(plo + nt * 8), make_float2(e0, e1));
                        __stcs((float2*)(phi + nt * 8), make_float2(e2, e3));
                    }
                } else {
                    float sl = 0.f, sh = 0.f;
#pragma unroll
                    for (int nt = 0; nt < 4; nt++) {
                        float2 bv = *(const float2*)&bsm[cb2 + nt * 8];
                        sl += __expf(acc[mt][nt][0] + bv.x) + __expf(acc[mt][nt][1] + bv.y);
                        sh += __expf(acc[mt][nt][2] + bv.x) + __expf(acc[mt][nt][3] + bv.y);
                    }
                    if (mt == 0) { slo0 += sl; shi0 += sh; }
                    else         { slo1 += sl; shi1 += sh; }
                }
            }
        }

        if (!STORE) {
            slo0 += __shfl_xor_sync(0xffffffffu, slo0, 1);
            slo0 += __shfl_xor_sync(0xffffffffu, slo0, 2);
            shi0 += __shfl_xor_sync(0xffffffffu, shi0, 1);
            shi0 += __shfl_xor_sync(0xffffffffu, shi0, 2);
            slo1 += __shfl_xor_sync(0xffffffffu, slo1, 1);
            slo1 += __shfl_xor_sync(0xffffffffu, slo1, 2);
            shi1 += __shfl_xor_sync(0xffffffffu, shi1, 1);
            shi1 += __shfl_xor_sync(0xffffffffu, shi1, 2);
            if (tig == 0) {
                int r0 = rb + wm * 32 + g;
                atomicAdd(&g_rowsum[r0], slo0);
                atomicAdd(&g_rowsum[r0 + 8], shi0);
                atomicAdd(&g_rowsum[r0 + 16], slo1);
                atomicAdd(&g_rowsum[r0 + 24], shi1);
            }
        }
    }
}

// ---------------- K6: labels + restore zero-invariant for g_agg / g_rowsum ----------------
__global__ void k6_fin(const int* __restrict__ edge_tokens,
                       const int* __restrict__ edge_index,
                       float* __restrict__ out) {
    int b = blockIdx.x, t = threadIdx.x;
    if (b < N_EDGES) {
        int dst = edge_index[N_EDGES + b];
        g_agg[dst * D_GNN + t] = 0.f;
    } else if (b < N_EDGES + 32) {
        g_rowsum[(b - N_EDGES) * 128 + t] = 0.f;
    } else {
        int idx = (b - N_EDGES - 32) * 128 + t;
        int e = idx >> 3;
        int tok = edge_tokens[idx];
        out[idx] = (float)((e == 0 && tok >= 4) ? tok : -100);
    }
}

// ---------------- launch ----------------
extern "C" void kernel_launch(void* const* d_in, const int* in_sizes, int n_in,
                              void* d_out, int out_size) {
    const int*   node_tokens = (const int*)d_in[0];
    const int*   edge_tokens = (const int*)d_in[1];
    const int*   edge_index  = (const int*)d_in[2];
    const float* emb    = (const float*)d_in[3];
    const float* W_self = (const float*)d_in[4];
    const float* W_nbr  = (const float*)d_in[5];
    const float* Wq     = (const float*)d_in[6];
    const float* Wk     = (const float*)d_in[7];
    const float* Wv     = (const float*)d_in[8];
    const float* Wo     = (const float*)d_in[9];
    const float* W1     = (const float*)d_in[10];
    const float* W2     = (const float*)d_in[11];
    const float* lmW    = (const float*)d_in[12];
    const float* lmb    = (const float*)d_in[13];
    float* out = (float*)d_out;

    k1_msg<<<N_EDGES / K1_EDGES, 256>>>(node_tokens, edge_tokens, edge_index, emb, W_nbr);
    k3_fused<<<N_EDGES / 4, 128>>>(node_tokens, edge_index, emb, W_self,
                                   Wq, Wk, Wv, Wo, W1, W2);
    k4_tc<false><<<dim3(250, 4), 256>>>(lmW, lmb, out);
    k4_tc<true><<<dim3(250, 4), 256>>>(lmW, lmb, out);
    k6_fin<<<N_EDGES + 32 + 128, 128>>>(edge_tokens, edge_index, out);
}

// round 14
// speedup vs baseline: 1.0627x; 1.0627x over previous
#include <cuda_runtime.h>
#include <cuda_bf16.h>
#include <cstdint>

#define N_NODES 100000
#define N_EDGES 2048
#define L_TOK 8
#define HID 64
#define D_IN 512      // L_TOK * HID
#define D_GNN 128
#define VOCAB 32000
#define FFN_D 256
#define NROWS (N_EDGES * 2)   // 4096 lm-head rows
#define LBL_OFF 16384         // labels occupy [0, 16384)
#define LOG2E 1.4426950408889634f

// ---------------- device scratch (no allocations allowed) ----------------
// Invariant: g_agg (touched rows) and g_rowsum are ZERO at kernel_launch entry.
// Statically zero-initialized; re-zeroed by k6_fin at the end of every call.
// g_xf holds x * log2e (bf16x2 fragment-major) so the lm-head epilogue can use exp2.
__device__ float g_agg[N_NODES * D_GNN];
__device__ uint32_t g_xf[256 * 4 * 128];
__device__ float g_rowsum[NROWS];

__device__ __forceinline__ uint32_t pack_bf16x2(float lo, float hi) {
    __nv_bfloat162 b = __float22bfloat162_rn(make_float2(lo, hi));
    return *(uint32_t*)&b;
}

// ---------------- K1: msg = (node_emb[src] + edge_emb) @ W_nbr; scatter-add at dst ----------------
#define K1_EDGES 8
__global__ __launch_bounds__(256) void k1_msg(const int* __restrict__ node_tokens,
                                              const int* __restrict__ edge_tokens,
                                              const int* __restrict__ edge_index,
                                              const float* __restrict__ emb,
                                              const float* __restrict__ W_nbr) {
    __shared__ float t_s[K1_EDGES][D_IN];
    __shared__ int s_src[K1_EDGES], s_dst[K1_EDGES];
    int b = blockIdx.x, tid = threadIdx.x;
    int e0 = b * K1_EDGES;
    if (tid < K1_EDGES) {
        s_src[tid] = edge_index[e0 + tid];
        s_dst[tid] = edge_index[N_EDGES + e0 + tid];
    }
    __syncthreads();
    for (int idx = tid; idx < K1_EDGES * D_IN; idx += 256) {
        int el = idx >> 9, kk = idx & 511;
        int l = kk >> 6, h = kk & 63;
        int tn = node_tokens[s_src[el] * L_TOK + l];
        int te = edge_tokens[(e0 + el) * L_TOK + l];
        t_s[el][kk] = emb[tn * HID + h] + emb[te * HID + h];
    }
    __syncthreads();
    int c = tid & 127, p = tid >> 7;
    float a0 = 0.f, a1 = 0.f, a2 = 0.f, a3 = 0.f;
    const float* t0 = t_s[4 * p + 0];
    const float* t1 = t_s[4 * p + 1];
    const float* t2 = t_s[4 * p + 2];
    const float* t3 = t_s[4 * p + 3];
#pragma unroll 8
    for (int k = 0; k < D_IN; k++) {
        float w = W_nbr[k * D_GNN + c];
        a0 += t0[k] * w;
        a1 += t1[k] * w;
        a2 += t2[k] * w;
        a3 += t3[k] * w;
    }
    atomicAdd(&g_agg[s_dst[4 * p + 0] * D_GNN + c], a0);
    atomicAdd(&g_agg[s_dst[4 * p + 1] * D_GNN + c], a1);
    atomicAdd(&g_agg[s_dst[4 * p + 2] * D_GNN + c], a2);
    atomicAdd(&g_agg[s_dst[4 * p + 3] * D_GNN + c], a3);
}

// ---------------- K3: fused GNN-h + transformer; WARP PER EDGE (2 rows/warp) ----------------
__global__ __launch_bounds__(128) void k3_fused(const int* __restrict__ node_tokens,
                                                const int* __restrict__ edge_index,
                                                const float* __restrict__ emb,
                                                const float* __restrict__ W_self,
                                                const float* __restrict__ Wq, const float* __restrict__ Wk,
                                                const float* __restrict__ Wv, const float* __restrict__ Wo,
                                                const float* __restrict__ W1, const float* __restrict__ W2) {
    __shared__ float ne[8][D_IN];
    __shared__ float hn[8][D_GNN];
    __shared__ int snode[8];
    __shared__ float xsm[4][2][64];
    __shared__ float hsm[4][2][FFN_D];

    int tid = threadIdx.x, lane = tid & 31, wid = tid >> 5;
    int e_base = blockIdx.x * 4;

    if (tid < 8)
        snode[tid] = edge_index[(tid & 1) * N_EDGES + e_base + (tid >> 1)];
    __syncthreads();

    for (int idx = tid; idx < 8 * D_IN; idx += 128) {
        int j = idx >> 9, kk = idx & 511;
        int l = kk >> 6, hcol = kk & 63;
        int tok = node_tokens[snode[j] * L_TOK + l];
        ne[j][kk] = emb[tok * HID + hcol];
    }
    __syncthreads();

    {
        int c = tid;
        float acc[8];
#pragma unroll
        for (int j = 0; j < 8; j++) acc[j] = 0.f;
#pragma unroll 2
        for (int k4i = 0; k4i < D_IN / 4; k4i++) {
            const float* wr = W_self + k4i * 4 * D_GNN + c;
            float w0 = wr[0], w1 = wr[D_GNN], w2 = wr[2 * D_GNN], w3 = wr[3 * D_GNN];
#pragma unroll
            for (int j = 0; j < 8; j++) {
                float4 a = ((const float4*)ne[j])[k4i];
                acc[j] += a.x * w0 + a.y * w1 + a.z * w2 + a.w * w3;
            }
        }
#pragma unroll
        for (int j = 0; j < 8; j++)
            hn[j][c] = fmaxf(acc[j] + g_agg[snode[j] * D_GNN + c], 0.f);
    }
    __syncthreads();

    int e = e_base + wid;
    float2 s0a = ((const float2*)&hn[2 * wid][0])[lane];
    float2 s0b = ((const float2*)&hn[2 * wid + 1][0])[lane];
    float2 s1a = ((const float2*)&hn[2 * wid][64])[lane];
    float2 s1b = ((const float2*)&hn[2 * wid + 1][64])[lane];
    float x00 = s0a.x + s0b.x, x01 = s0a.y + s0b.y;
    float x10 = s1a.x + s1b.x, x11 = s1a.y + s1b.y;
    xsm[wid][0][2 * lane] = x00; xsm[wid][0][2 * lane + 1] = x01;
    xsm[wid][1][2 * lane] = x10; xsm[wid][1][2 * lane + 1] = x11;
    __syncwarp();

    const float2* Wq2 = (const float2*)Wq;
    const float2* Wk2 = (const float2*)Wk;
    const float2* Wv2 = (const float2*)Wv;
    const float2* Wo2 = (const float2*)Wo;
    const float2* W22 = (const float2*)W2;

    float q00 = 0.f, q01 = 0.f, k00 = 0.f, k01 = 0.f, v00 = 0.f, v01 = 0.f;
    float q10 = 0.f, q11 = 0.f, k10 = 0.f, k11 = 0.f, v10 = 0.f, v11 = 0.f;
#pragma unroll 4
    for (int k = 0; k < 64; k++) {
        float xa = xsm[wid][0][k], xb = xsm[wid][1][k];
        float2 wq = Wq2[k * 32 + lane];
        float2 wk = Wk2[k * 32 + lane];
        float2 wv = Wv2[k * 32 + lane];
        q00 += xa * wq.x; q01 += xa * wq.y; q10 += xb * wq.x; q11 += xb * wq.y;
        k00 += xa * wk.x; k01 += xa * wk.y; k10 += xb * wk.x; k11 += xb * wk.y;
        v00 += xa * wv.x; v01 += xa * wv.y; v10 += xb * wv.x; v11 += xb * wv.y;
    }

    float p00 = q00 * k00 + q01 * k01;
    float p01 = q00 * k10 + q01 * k11;
    float p10 = q10 * k00 + q11 * k01;
    float p11 = q10 * k10 + q11 * k11;
#pragma unroll
    for (int d = 16; d; d >>= 1) {
        p00 += __shfl_xor_sync(0xffffffffu, p00, d);
        p01 += __shfl_xor_sync(0xffffffffu, p01, d);
        p10 += __shfl_xor_sync(0xffffffffu, p10, d);
        p11 += __shfl_xor_sync(0xffffffffu, p11, d);
    }
    p00 *= 0.125f; p01 *= 0.125f; p10 *= 0.125f; p11 *= 0.125f;
    float m0 = fmaxf(p00, p01), m1 = fmaxf(p10, p11);
    float e00 = __expf(p00 - m0), e01 = __expf(p01 - m0);
    float e10 = __expf(p10 - m1), e11 = __expf(p11 - m1);
    float i0 = 1.f / (e00 + e01), i1 = 1.f / (e10 + e11);
    float a00 = e00 * i0, a01 = e01 * i0;
    float a10 = e10 * i1, a11 = e11 * i1;

    float y00 = a00 * v00 + a01 * v10, y01 = a00 * v01 + a01 * v11;
    float y10 = a10 * v00 + a11 * v10, y11 = a10 * v01 + a11 * v11;

    xsm[wid][0][2 * lane] = y00; xsm[wid][0][2 * lane + 1] = y01;
    xsm[wid][1][2 * lane] = y10; xsm[wid][1][2 * lane + 1] = y11;
    __syncwarp();

    float o00 = 0.f, o01 = 0.f, o10 = 0.f, o11 = 0.f;
#pragma unroll 4
    for (int k = 0; k < 64; k++) {
        float ya = xsm[wid][0][k], yb = xsm[wid][1][k];
        float2 wo = Wo2[k * 32 + lane];
        o00 += ya * wo.x; o01 += ya * wo.y;
        o10 += yb * wo.x; o11 += yb * wo.y;
    }
    x00 += o00; x01 += o01; x10 += o10; x11 += o11;

    float ms0 = x00 + x01, ms1 = x10 + x11;
#pragma unroll
    for (int d = 16; d; d >>= 1) {
        ms0 += __shfl_xor_sync(0xffffffffu, ms0, d);
        ms1 += __shfl_xor_sync(0xffffffffu, ms1, d);
    }
    float mean0 = ms0 * (1.f / 64.f), mean1 = ms1 * (1.f / 64.f);
    float d00 = x00 - mean0, d01 = x01 - mean0;
    float d10 = x10 - mean1, d11 = x11 - mean1;
    float vs0 = d00 * d00 + d01 * d01, vs1 = d10 * d10 + d11 * d11;
#pragma unroll
    for (int d = 16; d; d >>= 1) {
        vs0 += __shfl_xor_sync(0xffffffffu, vs0, d);
        vs1 += __shfl_xor_sync(0xffffffffu, vs1, d);
    }
    float r0 = rsqrtf(vs0 * (1.f / 64.f) + 1e-5f);
    float r1 = rsqrtf(vs1 * (1.f / 64.f) + 1e-5f);
    x00 = d00 * r0; x01 = d01 * r0;
    x10 = d10 * r1; x11 = d11 * r1;

    __syncwarp();
    xsm[wid][0][2 * lane] = x00; xsm[wid][0][2 * lane + 1] = x01;
    xsm[wid][1][2 * lane] = x10; xsm[wid][1][2 * lane + 1] = x11;
    __syncwarp();

    float h[2][8];
#pragma unroll
    for (int j = 0; j < 8; j++) { h[0][j] = 0.f; h[1][j] = 0.f; }
#pragma unroll 4
    for (int k = 0; k < 64; k++) {
        float xa = xsm[wid][0][k], xb = xsm[wid][1][k];
        const float* w1r = W1 + k * FFN_D + lane;
#pragma unroll
        for (int j = 0; j < 8; j++) {
            float w = w1r[j * 32];
            h[0][j] += xa * w;
            h[1][j] += xb * w;
        }
    }
#pragma unroll
    for (int j = 0; j < 8; j++) {
        hsm[wid][0][j * 32 + lane] = fmaxf(h[0][j], 0.f);
        hsm[wid][1][j * 32 + lane] = fmaxf(h[1][j], 0.f);
    }
    __syncwarp();

    float o200 = 0.f, o201 = 0.f, o210 = 0.f, o211 = 0.f;
#pragma unroll 8
    for (int f = 0; f < FFN_D; f++) {
        float ha = hsm[wid][0][f], hb = hsm[wid][1][f];
        float2 w2 = W22[f * 32 + lane];
        o200 += ha * w2.x; o201 += ha * w2.y;
        o210 += hb * w2.x; o211 += hb * w2.y;
    }
    float z00 = x00 + o200, z01 = x01 + o201;
    float z10 = x10 + o210, z11 = x11 + o211;

    ms0 = z00 + z01; ms1 = z10 + z11;
#pragma unroll
    for (int d = 16; d; d >>= 1) {
        ms0 += __shfl_xor_sync(0xffffffffu, ms0, d);
        ms1 += __shfl_xor_sync(0xffffffffu, ms1, d);
    }
    mean0 = ms0 * (1.f / 64.f); mean1 = ms1 * (1.f / 64.f);
    d00 = z00 - mean0; d01 = z01 - mean0;
    d10 = z10 - mean1; d11 = z11 - mean1;
    vs0 = d00 * d00 + d01 * d01; vs1 = d10 * d10 + d11 * d11;
#pragma unroll
    for (int d = 16; d; d >>= 1) {
        vs0 += __shfl_xor_sync(0xffffffffu, vs0, d);
        vs1 += __shfl_xor_sync(0xffffffffu, vs1, d);
    }
    r0 = rsqrtf(vs0 * (1.f / 64.f) + 1e-5f) * LOG2E;   // fold log2e into x for exp2 epilogue
    r1 = rsqrtf(vs1 * (1.f / 64.f) + 1e-5f) * LOG2E;

    {
        int ks = lane >> 3, pr = lane & 7, hi = pr >> 2, tg = pr & 3;
        int frag = ks * 128 + tg * 2 + hi;
#pragma unroll
        for (int s = 0; s < 2; s++) {
            int rr = e * 2 + s;
            int rt16 = rr >> 4, half = (rr & 15) >> 3, gg = rr & 7;
            float lo = (s == 0 ? d00 * r0 : d10 * r1);
            float hi2 = (s == 0 ? d01 * r0 : d11 * r1);
            g_xf[rt16 * 512 + frag + half * 64 + gg * 8] = pack_bf16x2(lo, hi2);
        }
    }
}

// ---------------- K4: lm head, bf16 m16n8k16; B-resident; two-pass; exp2 epilogue ----------------
// (Round-12 configuration: 64-col accumulators, 2 blocks/SM, __stcs stores.)
#define K4_ROW_ITERS 8

template <bool STORE>
__global__ __launch_bounds__(256, 2) void k4_tc(const float* __restrict__ lmW,
                                                const float* __restrict__ lmb,
                                                float* __restrict__ out) {
    __shared__ uint32_t Bs[4096];
    __shared__ float bsm[128];

    int tid = threadIdx.x;
    int cb = blockIdx.x * 128;

    for (int i = tid; i < 4096; i += 256) {
        int n = i & 127, w = i >> 7;
        float v0 = lmW[(size_t)(2 * w) * VOCAB + cb + n];
        float v1 = lmW[(size_t)(2 * w + 1) * VOCAB + cb + n];
        int nt = n >> 3, gg = n & 7;
        int ks = w >> 3, pr = w & 7, hi = pr >> 2, tg = pr & 3;
        Bs[(nt * 4 + ks) * 64 + gg * 8 + tg * 2 + hi] = pack_bf16x2(v0, v1);
    }
    if (tid < 128) bsm[tid] = lmb[cb + tid] * LOG2E;   // bias pre-scaled for exp2
    __syncthreads();

    int lane = tid & 31, warp = tid >> 5;
    int wm = warp >> 1, wn = warp & 1;
    int g = lane >> 2, tig = lane & 3;

    float2 bv[8];
#pragma unroll
    for (int nt = 0; nt < 8; nt++)
        bv[nt] = *(const float2*)&bsm[wn * 64 + nt * 8 + 2 * tig];

#pragma unroll 1
    for (int it = 0; it < K4_ROW_ITERS; it++) {
        int rb = (blockIdx.y * K4_ROW_ITERS + it) * 128;
        int rt16b = rb >> 4;

        float acc[2][8][4];
#pragma unroll
        for (int mt = 0; mt < 2; mt++)
#pragma unroll
            for (int nt = 0; nt < 8; nt++)
#pragma unroll
                for (int j = 0; j < 4; j++) acc[mt][nt][j] = 0.f;

#pragma unroll
        for (int ks = 0; ks < 4; ks++) {
            uint32_t a[2][4];
#pragma unroll
            for (int mt = 0; mt < 2; mt++) {
                const uint32_t* ap = g_xf + ((rt16b + wm * 2 + mt) * 4 + ks) * 128;
                uint2 p0 = __ldg((const uint2*)(ap + lane * 2));
                uint2 p1 = __ldg((const uint2*)(ap + 64 + lane * 2));
                a[mt][0] = p0.x; a[mt][2] = p0.y; a[mt][1] = p1.x; a[mt][3] = p1.y;
            }
#pragma unroll
            for (int nt = 0; nt < 8; nt++) {
                const uint32_t* bp = Bs + ((wn * 8 + nt) * 4 + ks) * 64;
                uint2 bb = *(const uint2*)(bp + lane * 2);
#pragma unroll
                for (int mt = 0; mt < 2; mt++) {
                    asm volatile(
                        "mma.sync.aligned.m16n8k16.row.col.f32.bf16.bf16.f32 "
                        "{%0,%1,%2,%3}, {%4,%5,%6,%7}, {%8,%9}, {%0,%1,%2,%3};\n"
                        : "+f"(acc[mt][nt][0]), "+f"(acc[mt][nt][1]),
                          "+f"(acc[mt][nt][2]), "+f"(acc[mt][nt][3])
                        : "r"(a[mt][0]), "r"(a[mt][1]), "r"(a[mt][2]), "r"(a[mt][3]),
                          "r"(bb.x), "r"(bb.y));
                }
            }
        }

#pragma unroll
        for (int mt = 0; mt < 2; mt++) {
            int r_lo = rb + wm * 32 + mt * 16 + g;
            if (STORE) {
                float inv_lo = 1.f / g_rowsum[r_lo];
                float inv_hi = 1.f / g_rowsum[r_lo + 8];
                float* plo = out + (size_t)LBL_OFF + (size_t)r_lo * VOCAB + cb + wn * 64 + 2 * tig;
                float* phi = plo + (size_t)8 * VOCAB;
#pragma unroll
                for (int nt = 0; nt < 8; nt++) {
                    float e0 = exp2f(acc[mt][nt][0] + bv[nt].x) * inv_lo;
                    float e1 = exp2f(acc[mt][nt][1] + bv[nt].y) * inv_lo;
                    float e2 = exp2f(acc[mt][nt][2] + bv[nt].x) * inv_hi;
                    float e3 = exp2f(acc[mt][nt][3] + bv[nt].y) * inv_hi;
                    __stcs((float2*)(plo + nt * 8), make_float2(e0, e1));
                    __stcs((float2*)(phi + nt * 8), make_float2(e2, e3));
                }
            } else {
                float slo = 0.f, shi = 0.f;
#pragma unroll
                for (int nt = 0; nt < 8; nt++) {
                    slo += exp2f(acc[mt][nt][0] + bv[nt].x) + exp2f(acc[mt][nt][1] + bv[nt].y);
                    shi += exp2f(acc[mt][nt][2] + bv[nt].x) + exp2f(acc[mt][nt][3] + bv[nt].y);
                }
                slo += __shfl_xor_sync(0xffffffffu, slo, 1);
                slo += __shfl_xor_sync(0xffffffffu, slo, 2);
                shi += __shfl_xor_sync(0xffffffffu, shi, 1);
                shi += __shfl_xor_sync(0xffffffffu, shi, 2);
                if (tig == 0) {
                    atomicAdd(&g_rowsum[r_lo], slo);
                    atomicAdd(&g_rowsum[r_lo + 8], shi);
                }
            }
        }
    }
}

// ---------------- K6: labels + restore zero-invariant for g_agg / g_rowsum ----------------
__global__ void k6_fin(const int* __restrict__ edge_tokens,
                       const int* __restrict__ edge_index,
                       float* __restrict__ out) {
    int b = blockIdx.x, t = threadIdx.x;
    if (b < N_EDGES) {
        int dst = edge_index[N_EDGES + b];
        g_agg[dst * D_GNN + t] = 0.f;
    } else if (b < N_EDGES + 32) {
        g_rowsum[(b - N_EDGES) * 128 + t] = 0.f;
    } else {
        int idx = (b - N_EDGES - 32) * 128 + t;
        int e = idx >> 3;
        int tok = edge_tokens[idx];
        out[idx] = (float)((e == 0 && tok >= 4) ? tok : -100);
    }
}

// ---------------- launch ----------------
extern "C" void kernel_launch(void* const* d_in, const int* in_sizes, int n_in,
                              void* d_out, int out_size) {
    const int*   node_tokens = (const int*)d_in[0];
    const int*   edge_tokens = (const int*)d_in[1];
    const int*   edge_index  = (const int*)d_in[2];
    const float* emb    = (const float*)d_in[3];
    const float* W_self = (const float*)d_in[4];
    const float* W_nbr  = (const float*)d_in[5];
    const float* Wq     = (const float*)d_in[6];
    const float* Wk     = (const float*)d_in[7];
    const float* Wv     = (const float*)d_in[8];
    const float* Wo     = (const float*)d_in[9];
    const float* W1     = (const float*)d_in[10];
    const float* W2     = (const float*)d_in[11];
    const float* lmW    = (const float*)d_in[12];
    const float* lmb    = (const float*)d_in[13];
    float* out = (float*)d_out;

    k1_msg<<<N_EDGES / K1_EDGES, 256>>>(node_tokens, edge_tokens, edge_index, emb, W_nbr);
    k3_fused<<<N_EDGES / 4, 128>>>(node_tokens, edge_index, emb, W_self,
                                   Wq, Wk, Wv, Wo, W1, W2);
    k4_tc<false><<<dim3(250, 4), 256>>>(lmW, lmb, out);
    k4_tc<true><<<dim3(250, 4), 256>>>(lmW, lmb, out);
    k6_fin<<<N_EDGES + 32 + 128, 128>>>(edge_tokens, edge_index, out);
}